// round 14
// baseline (speedup 1.0000x reference)
#include <cuda_runtime.h>
#include <cstdint>
#include <cuda_fp16.h>

#define B_ 8
#define E_ 512
#define L_ 8192
#define KS_ 5
#define LC_ (L_ - KS_ + 1)   // 8188
#define NB3_ 2730
#define KT_ (E_ * KS_)       // 2560

// conv tiling: CTA 128eo x 256t, 16 warps of 64x32; K chunks of 32 (5 taps x 16 e-chunks)
// fp16 2-product: A = W (single tile), B = X (hi/lo tiles)
#define NCH 80
#define ROWB 80                       // padded smem row stride (64B payload)
#define A_TILE (128 * ROWB)           // 10240, one tile per stage
#define B_ROWS 260
#define B_TILE (B_ROWS * ROWB)        // 20800
#define B_BUF (2 * B_TILE)            // 41600 (hi + lo)
#define OFF_B (3 * A_TILE)            // 30720
#define CSMEM (OFF_B + 2 * B_BUF)     // 113920

__device__ float g_y[(size_t)B_ * E_ * L_];
__device__ float g_s[(size_t)B_ * L_];
__device__ __align__(16) __half g_xth[(size_t)B_ * L_ * E_]; // [b][t][e] hi
__device__ __align__(16) __half g_xtl[(size_t)B_ * L_ * E_]; // [b][t][e] lo
__device__ __align__(16) __half g_wh[(size_t)E_ * KT_];      // [eo][tap][ein]

__device__ __forceinline__ uint32_t smem_u32(const void* p) {
    uint32_t a;
    asm("{ .reg .u64 t; cvta.to.shared.u64 t, %1; cvt.u32.u64 %0, t; }" : "=r"(a) : "l"(p));
    return a;
}
#define CP16(dst, src) \
    asm volatile("cp.async.cg.shared.global [%0], [%1], 16;" :: "r"(dst), "l"(src) : "memory")
#define CP_COMMIT() asm volatile("cp.async.commit_group;" ::: "memory")
#define CP_WAIT1() asm volatile("cp.async.wait_group 1;" ::: "memory")

#define LDSM4(r, a) \
    asm volatile("ldmatrix.sync.aligned.m8n8.x4.shared.b16 {%0,%1,%2,%3}, [%4];" \
        : "=r"((r)[0]), "=r"((r)[1]), "=r"((r)[2]), "=r"((r)[3]) : "r"(a))

#define MMA(c, A, b0, b1) \
    asm volatile("mma.sync.aligned.m16n8k16.row.col.f32.f16.f16.f32 " \
        "{%0,%1,%2,%3},{%4,%5,%6,%7},{%8,%9},{%0,%1,%2,%3};" \
        : "+f"((c)[0]), "+f"((c)[1]), "+f"((c)[2]), "+f"((c)[3]) \
        : "r"((A)[0]), "r"((A)[1]), "r"((A)[2]), "r"((A)[3]), "r"(b0), "r"(b1))

// ---- transpose + hi/lo fp16 split of x: [b][e][t] f32 -> [b][t][e] ----
__global__ __launch_bounds__(256) void tsplit_x(const float* __restrict__ x) {
    __shared__ float tile[32][33];
    const int b = blockIdx.z, t0 = blockIdx.x * 32, e0 = blockIdx.y * 32;
    const int tx = threadIdx.x & 31, ty = threadIdx.x >> 5;
#pragma unroll
    for (int p = 0; p < 4; p++)
        tile[ty + 8 * p][tx] = x[((size_t)b * E_ + e0 + ty + 8 * p) * L_ + t0 + tx];
    __syncthreads();
#pragma unroll
    for (int p = 0; p < 4; p++) {
        int t = t0 + ty + 8 * p;
        float v = tile[tx][ty + 8 * p];
        __half h = __float2half(v);
        __half l = __float2half(v - __half2float(h));
        size_t o = ((size_t)b * L_ + t) * E_ + e0 + tx;
        g_xth[o] = h;
        g_xtl[o] = l;
    }
}

// ---- weight re-layout: w[eo][ein][tap] -> [eo][tap][ein] fp16 ----
__global__ __launch_bounds__(256) void split_w(const float* __restrict__ w) {
    int i = blockIdx.x * 256 + threadIdx.x;
    int eo = i / KT_;
    int r = i - eo * KT_;
    int tap = r >> 9, ei = r & 511;
    g_wh[i] = __float2half(w[(size_t)eo * KT_ + ei * KS_ + tap]);
}

// ---- conv: C[eo 128][t 256], 16 warps (64x32), 2-product fp16 ----
__global__ __launch_bounds__(512, 1) void conv_mma(const float* __restrict__ bias) {
    extern __shared__ __align__(16) char sm[];
    const uint32_t sb = smem_u32(sm);
    const int tid = threadIdx.x, lane = tid & 31, wid = tid >> 5;
    const int wm = wid & 1;        // eo 64-half
    const int wn = wid >> 1;       // t 32-block (0..7)
    const int b = blockIdx.z, t0 = blockIdx.x * 256, eo0 = blockIdx.y * 128;

    float acc[4][4][4];
#pragma unroll
    for (int i = 0; i < 4; i++)
#pragma unroll
        for (int j = 0; j < 4; j++)
#pragma unroll
            for (int q = 0; q < 4; q++) acc[i][j][q] = 0.f;

    const int lrow = tid >> 2, lq = tid & 3;   // 128 loader rows x 4 16B-chunks

    auto issue = [&](int c) {
        const int tap = c % KS_, ec = c / KS_;
        const uint32_t stA = sb + (c % 3) * A_TILE;
        const size_t woff = (size_t)(eo0 + lrow) * KT_ + tap * 512 + ec * 32 + lq * 8;
        CP16(stA + lrow * ROWB + lq * 16, g_wh + woff);
        if (tap == 0) {
            const uint32_t stB = sb + OFF_B + (ec & 1) * B_BUF;
#pragma unroll
            for (int h = 0; h < 2; h++) {
                int r = lrow + h * 128;
                int t = t0 + r; if (t > L_ - 1) t = L_ - 1;
                const size_t xoff = ((size_t)b * L_ + t) * E_ + ec * 32 + lq * 8;
                CP16(stB + r * ROWB + lq * 16, g_xth + xoff);
                CP16(stB + B_TILE + r * ROWB + lq * 16, g_xtl + xoff);
            }
            if (lrow < 4) {
                int r = 256 + lrow;
                int t = t0 + r; if (t > L_ - 1) t = L_ - 1;
                const size_t xoff = ((size_t)b * L_ + t) * E_ + ec * 32 + lq * 8;
                CP16(stB + r * ROWB + lq * 16, g_xth + xoff);
                CP16(stB + B_TILE + r * ROWB + lq * 16, g_xtl + xoff);
            }
        }
    };

    issue(0); CP_COMMIT();
    issue(1); CP_COMMIT();

    const int lr = lane & 7, g = lane >> 3;

    for (int c = 0; c < NCH; c++) {
        CP_WAIT1();        // group c landed (only c+1 may remain in flight)
        __syncthreads();   // protects stage (c+2)%3 overwrites issued below

        const int tap = c % KS_;
        const uint32_t stA = sb + (c % 3) * A_TILE;
        const uint32_t stB = sb + OFF_B + ((c / KS_) & 1) * B_BUF;

        uint32_t bh[2][4][2], bl[2][4][2];   // X hi/lo frags, double-buffered across kk
        auto loadB = [&](int kk) {
#pragma unroll
            for (int j = 0; j < 2; j++) {
                uint32_t rb = stB
                    + (uint32_t)(tap + wn * 32 + j * 16 + lr + (g >> 1) * 8) * ROWB
                    + kk * 32 + (g & 1) * 16;
                uint32_t r4[4];
                LDSM4(r4, rb);
                bh[kk][2 * j][0] = r4[0]; bh[kk][2 * j][1] = r4[1];
                bh[kk][2 * j + 1][0] = r4[2]; bh[kk][2 * j + 1][1] = r4[3];
                LDSM4(r4, rb + B_TILE);
                bl[kk][2 * j][0] = r4[0]; bl[kk][2 * j][1] = r4[1];
                bl[kk][2 * j + 1][0] = r4[2]; bl[kk][2 * j + 1][1] = r4[3];
            }
        };

        loadB(0);
#pragma unroll
        for (int kk = 0; kk < 2; kk++) {
            uint32_t af[4][4];
#pragma unroll
            for (int i = 0; i < 4; i++) {
                uint32_t ra = stA + (uint32_t)(wm * 64 + i * 16 + lr + (g & 1) * 8) * ROWB
                              + kk * 32 + (g >> 1) * 16;
                LDSM4(af[i], ra);
            }
            if (kk == 0) loadB(1);   // prefetch next-kk B under the MMAs
#pragma unroll
            for (int i = 0; i < 4; i++)
#pragma unroll
                for (int j = 0; j < 4; j++) {
                    MMA(acc[i][j], af[i], bh[kk][j][0], bh[kk][j][1]);
                    MMA(acc[i][j], af[i], bl[kk][j][0], bl[kk][j][1]);
                }
        }

        if (c + 2 < NCH) issue(c + 2);
        CP_COMMIT();
    }

    // store: acc -> g_y + bias, zero for t >= LC_
    const int l4 = lane >> 2, l2 = (lane & 3) * 2;
#pragma unroll
    for (int i = 0; i < 4; i++) {
        int eoA = eo0 + wm * 64 + i * 16 + l4;
        float bv0 = bias[eoA], bv1 = bias[eoA + 8];
        float* p0 = g_y + ((size_t)b * E_ + eoA) * L_;
        float* p1 = p0 + (size_t)8 * L_;
#pragma unroll
        for (int j = 0; j < 4; j++) {
            int tc = t0 + wn * 32 + j * 8 + l2;
            float2 v0, v1;
            v0.x = (tc     < LC_) ? acc[i][j][0] + bv0 : 0.f;
            v0.y = (tc + 1 < LC_) ? acc[i][j][1] + bv0 : 0.f;
            v1.x = (tc     < LC_) ? acc[i][j][2] + bv1 : 0.f;
            v1.y = (tc + 1 < LC_) ? acc[i][j][3] + bv1 : 0.f;
            *reinterpret_cast<float2*>(p0 + tc) = v0;
            *reinterpret_cast<float2*>(p1 + tc) = v1;
        }
    }
}

// ---- scores s[b,t] = <y[b,:,t], score_w>, 4-way e-split ----
__global__ __launch_bounds__(256) void score_kernel(const float* __restrict__ sw) {
    __shared__ float swv[E_];
    __shared__ float red[4][64];
    const int tid = threadIdx.x;
    const int b = blockIdx.y;
    const int tl = tid & 63;
    const int eg = tid >> 6;
    const int t = blockIdx.x * 64 + tl;
    for (int i = tid; i < E_; i += 256) swv[i] = sw[i];
    __syncthreads();
    const float* yb = g_y + (size_t)b * E_ * L_ + (size_t)eg * 128 * L_ + t;
    float acc = 0.f;
#pragma unroll 16
    for (int e = 0; e < 128; e++) acc += yb[(size_t)e * L_] * swv[eg * 128 + e];
    red[eg][tl] = acc;
    __syncthreads();
    if (eg == 0)
        g_s[(size_t)b * L_ + t] = red[0][tl] + red[1][tl] + red[2][tl] + red[3][tl];
}

// ---- softmax mix + downsample ----
#define OT 32
__global__ __launch_bounds__(256) void epilogue_kernel(float* __restrict__ out) {
    __shared__ float att[2 * OT][3];
    const int b = blockIdx.y, o0 = blockIdx.x * OT, tid = threadIdx.x;
    const float* sp = g_s + (size_t)b * L_;

    if (tid < 2 * OT) {
        int l = 2 * o0 + tid;
        float c1 = sp[l];
        int n2 = l >> 1;
        float c2 = 0.5f * (sp[2 * n2] + sp[2 * n2 + 1]);
        int n3 = l / 3;
        float c3 = (n3 < NB3_) ? (sp[3 * n3] + sp[3 * n3 + 1] + sp[3 * n3 + 2]) * (1.f / 3.f) : 0.f;
        float m = fmaxf(c1, fmaxf(c2, c3));
        float a1 = __expf(c1 - m), a2 = __expf(c2 - m), a3 = __expf(c3 - m);
        float inv = 1.f / (a1 + a2 + a3);
        att[tid][0] = a1 * inv; att[tid][1] = a2 * inv; att[tid][2] = a3 * inv;
    }
    __syncthreads();

    const float* yb = g_y + (size_t)b * E_ * L_;
    const int ol = tid & (OT - 1), o = o0 + ol;
    const int l0 = 2 * o, l1 = l0 + 1;
    const int n3a = l0 / 3, n3b = l1 / 3;
    const bool ok3a = (n3a < NB3_), ok3b = (n3b < NB3_);
    const float w10 = att[2 * ol][0], w20 = att[2 * ol][1], w30 = att[2 * ol][2];
    const float w11 = att[2 * ol + 1][0], w21 = att[2 * ol + 1][1], w31 = att[2 * ol + 1][2];

    for (int e = tid / OT; e < E_; e += 256 / OT) {
        const float* yr = yb + (size_t)e * L_;
        float ya = yr[l0], yv = yr[l1];
        float v2 = 0.5f * (ya + yv);
        float v3a = ok3a ? (yr[3 * n3a] + yr[3 * n3a + 1] + yr[3 * n3a + 2]) * (1.f / 3.f) : 0.f;
        float v3b = (n3b == n3a) ? v3a
                  : (ok3b ? (yr[3 * n3b] + yr[3 * n3b + 1] + yr[3 * n3b + 2]) * (1.f / 3.f) : 0.f);
        out[((size_t)b * E_ + e) * (L_ / 2) + o] =
            0.5f * ((ya * w10 + v2 * w20 + v3a * w30) + (yv * w11 + v2 * w21 + v3b * w31));
    }
}

extern "C" void kernel_launch(void* const* d_in, const int* in_sizes, int n_in,
                              void* d_out, int out_size) {
    const float* x = (const float*)d_in[0];
    const float* conv_w = (const float*)d_in[1];
    const float* conv_b = (const float*)d_in[2];
    const float* score_w = (const float*)d_in[3];
    float* out = (float*)d_out;

    dim3 gt(L_ / 32, E_ / 32, B_);
    tsplit_x<<<gt, 256>>>(x);
    split_w<<<(E_ * KT_) / 256, 256>>>(conv_w);

    static int smem_set = 0;
    if (!smem_set) {
        cudaFuncSetAttribute(conv_mma, cudaFuncAttributeMaxDynamicSharedMemorySize, CSMEM);
        smem_set = 1;
    }
    dim3 gc(L_ / 256, E_ / 128, B_);   // 32 x 4 x 8 = 1024 CTAs
    conv_mma<<<gc, 512, CSMEM>>>(conv_b);

    dim3 gs(L_ / 64, B_);
    score_kernel<<<gs, 256>>>(score_w);

    dim3 ge((L_ / 2) / OT, B_);
    epilogue_kernel<<<ge, 256>>>(out);
}

// round 16
// speedup vs baseline: 2.2429x; 2.2429x over previous
#include <cuda_runtime.h>
#include <cstdint>
#include <cuda_fp16.h>

#define B_ 8
#define E_ 512
#define L_ 8192
#define KS_ 5
#define LC_ (L_ - KS_ + 1)   // 8188
#define NB3_ 2730
#define KT_ (E_ * KS_)       // 2560

// conv tiling: CTA 128eo x 256t, 16 warps of 64x32; K chunks of 32 (5 taps x 16 e-chunks)
// single-product fp16: A = W, B = X
#define NCH 80
#define ROWB 80                       // padded smem row stride (64B payload)
#define A_TILE (128 * ROWB)           // 10240, 3 stages
#define B_ROWS 260
#define B_TILE (B_ROWS * ROWB)        // 20800, double-buffered
#define OFF_B (3 * A_TILE)            // 30720
#define CSMEM (OFF_B + 2 * B_TILE)    // 72320

__device__ float g_y[(size_t)B_ * E_ * L_];
__device__ float g_s[(size_t)B_ * L_];
__device__ __align__(16) __half g_xt[(size_t)B_ * L_ * E_]; // [b][t][e]
__device__ __align__(16) __half g_w[(size_t)E_ * KT_];      // [eo][tap][ein]

__device__ __forceinline__ uint32_t smem_u32(const void* p) {
    uint32_t a;
    asm("{ .reg .u64 t; cvta.to.shared.u64 t, %1; cvt.u32.u64 %0, t; }" : "=r"(a) : "l"(p));
    return a;
}
#define CP16(dst, src) \
    asm volatile("cp.async.cg.shared.global [%0], [%1], 16;" :: "r"(dst), "l"(src) : "memory")
#define CP_COMMIT() asm volatile("cp.async.commit_group;" ::: "memory")
#define CP_WAIT1() asm volatile("cp.async.wait_group 1;" ::: "memory")

#define LDSM4(r, a) \
    asm volatile("ldmatrix.sync.aligned.m8n8.x4.shared.b16 {%0,%1,%2,%3}, [%4];" \
        : "=r"((r)[0]), "=r"((r)[1]), "=r"((r)[2]), "=r"((r)[3]) : "r"(a))

#define MMA(c, A, b0, b1) \
    asm volatile("mma.sync.aligned.m16n8k16.row.col.f32.f16.f16.f32 " \
        "{%0,%1,%2,%3},{%4,%5,%6,%7},{%8,%9},{%0,%1,%2,%3};" \
        : "+f"((c)[0]), "+f"((c)[1]), "+f"((c)[2]), "+f"((c)[3]) \
        : "r"((A)[0]), "r"((A)[1]), "r"((A)[2]), "r"((A)[3]), "r"(b0), "r"(b1))

// ---- transpose + fp16 quantize of x: [b][e][t] f32 -> [b][t][e] ----
__global__ __launch_bounds__(256) void tsplit_x(const float* __restrict__ x) {
    __shared__ float tile[32][33];
    const int b = blockIdx.z, t0 = blockIdx.x * 32, e0 = blockIdx.y * 32;
    const int tx = threadIdx.x & 31, ty = threadIdx.x >> 5;
#pragma unroll
    for (int p = 0; p < 4; p++)
        tile[ty + 8 * p][tx] = x[((size_t)b * E_ + e0 + ty + 8 * p) * L_ + t0 + tx];
    __syncthreads();
#pragma unroll
    for (int p = 0; p < 4; p++) {
        int t = t0 + ty + 8 * p;
        g_xt[((size_t)b * L_ + t) * E_ + e0 + tx] = __float2half(tile[tx][ty + 8 * p]);
    }
}

// ---- weight re-layout: w[eo][ein][tap] -> [eo][tap][ein] fp16 ----
__global__ __launch_bounds__(256) void split_w(const float* __restrict__ w) {
    int i = blockIdx.x * 256 + threadIdx.x;
    int eo = i / KT_;
    int r = i - eo * KT_;
    int tap = r >> 9, ei = r & 511;
    g_w[i] = __float2half(w[(size_t)eo * KT_ + ei * KS_ + tap]);
}

// ---- conv: C[eo 128][t 256], 16 warps (64x32), single-product fp16 ----
__global__ __launch_bounds__(512, 1) void conv_mma(const float* __restrict__ bias) {
    extern __shared__ __align__(16) char sm[];
    const uint32_t sb = smem_u32(sm);
    const int tid = threadIdx.x, lane = tid & 31, wid = tid >> 5;
    const int wm = wid & 1;        // eo 64-half
    const int wn = wid >> 1;       // t 32-block (0..7)
    const int b = blockIdx.z, t0 = blockIdx.x * 256, eo0 = blockIdx.y * 128;

    float acc[4][4][4];
#pragma unroll
    for (int i = 0; i < 4; i++)
#pragma unroll
        for (int j = 0; j < 4; j++)
#pragma unroll
            for (int q = 0; q < 4; q++) acc[i][j][q] = 0.f;

    const int lrow = tid >> 2, lq = tid & 3;   // 128 loader rows x 4 16B-chunks

    auto issue = [&](int c) {
        const int tap = c % KS_, ec = c / KS_;
        const uint32_t stA = sb + (c % 3) * A_TILE;
        const size_t woff = (size_t)(eo0 + lrow) * KT_ + tap * 512 + ec * 32 + lq * 8;
        CP16(stA + lrow * ROWB + lq * 16, g_w + woff);
        if (tap == 0) {
            const uint32_t stB = sb + OFF_B + (ec & 1) * B_TILE;
#pragma unroll
            for (int h = 0; h < 2; h++) {
                int r = lrow + h * 128;
                int t = t0 + r; if (t > L_ - 1) t = L_ - 1;
                CP16(stB + r * ROWB + lq * 16,
                     g_xt + ((size_t)b * L_ + t) * E_ + ec * 32 + lq * 8);
            }
            if (lrow < 4) {
                int r = 256 + lrow;
                int t = t0 + r; if (t > L_ - 1) t = L_ - 1;
                CP16(stB + r * ROWB + lq * 16,
                     g_xt + ((size_t)b * L_ + t) * E_ + ec * 32 + lq * 8);
            }
        }
    };

    issue(0); CP_COMMIT();
    issue(1); CP_COMMIT();

    const int lr = lane & 7, g = lane >> 3;

    for (int c = 0; c < NCH; c++) {
        CP_WAIT1();        // group c landed (only c+1 may remain in flight)
        __syncthreads();   // protects stage (c+2)%3 overwrites issued below

        const int tap = c % KS_;
        const uint32_t stA = sb + (c % 3) * A_TILE;
        const uint32_t stB = sb + OFF_B + ((c / KS_) & 1) * B_TILE;

        uint32_t bf[2][4][2];   // B frags double-buffered across kk
        auto loadB = [&](int kk) {
#pragma unroll
            for (int j = 0; j < 2; j++) {
                uint32_t rb = stB
                    + (uint32_t)(tap + wn * 32 + j * 16 + lr + (g >> 1) * 8) * ROWB
                    + kk * 32 + (g & 1) * 16;
                uint32_t r4[4];
                LDSM4(r4, rb);
                bf[kk][2 * j][0] = r4[0]; bf[kk][2 * j][1] = r4[1];
                bf[kk][2 * j + 1][0] = r4[2]; bf[kk][2 * j + 1][1] = r4[3];
            }
        };

        loadB(0);
#pragma unroll
        for (int kk = 0; kk < 2; kk++) {
            uint32_t af[4][4];
#pragma unroll
            for (int i = 0; i < 4; i++) {
                uint32_t ra = stA + (uint32_t)(wm * 64 + i * 16 + lr + (g & 1) * 8) * ROWB
                              + kk * 32 + (g >> 1) * 16;
                LDSM4(af[i], ra);
            }
            if (kk == 0) loadB(1);   // prefetch next-kk B under the MMAs
#pragma unroll
            for (int i = 0; i < 4; i++)
#pragma unroll
                for (int j = 0; j < 4; j++)
                    MMA(acc[i][j], af[i], bf[kk][j][0], bf[kk][j][1]);
        }

        if (c + 2 < NCH) issue(c + 2);
        CP_COMMIT();
    }

    // store: acc -> g_y + bias, zero for t >= LC_
    const int l4 = lane >> 2, l2 = (lane & 3) * 2;
#pragma unroll
    for (int i = 0; i < 4; i++) {
        int eoA = eo0 + wm * 64 + i * 16 + l4;
        float bv0 = bias[eoA], bv1 = bias[eoA + 8];
        float* p0 = g_y + ((size_t)b * E_ + eoA) * L_;
        float* p1 = p0 + (size_t)8 * L_;
#pragma unroll
        for (int j = 0; j < 4; j++) {
            int tc = t0 + wn * 32 + j * 8 + l2;
            float2 v0, v1;
            v0.x = (tc     < LC_) ? acc[i][j][0] + bv0 : 0.f;
            v0.y = (tc + 1 < LC_) ? acc[i][j][1] + bv0 : 0.f;
            v1.x = (tc     < LC_) ? acc[i][j][2] + bv1 : 0.f;
            v1.y = (tc + 1 < LC_) ? acc[i][j][3] + bv1 : 0.f;
            *reinterpret_cast<float2*>(p0 + tc) = v0;
            *reinterpret_cast<float2*>(p1 + tc) = v1;
        }
    }
}

// ---- scores s[b,t] = <y[b,:,t], score_w>, 4-way e-split ----
__global__ __launch_bounds__(256) void score_kernel(const float* __restrict__ sw) {
    __shared__ float swv[E_];
    __shared__ float red[4][64];
    const int tid = threadIdx.x;
    const int b = blockIdx.y;
    const int tl = tid & 63;
    const int eg = tid >> 6;
    const int t = blockIdx.x * 64 + tl;
    for (int i = tid; i < E_; i += 256) swv[i] = sw[i];
    __syncthreads();
    const float* yb = g_y + (size_t)b * E_ * L_ + (size_t)eg * 128 * L_ + t;
    float acc = 0.f;
#pragma unroll 16
    for (int e = 0; e < 128; e++) acc += yb[(size_t)e * L_] * swv[eg * 128 + e];
    red[eg][tl] = acc;
    __syncthreads();
    if (eg == 0)
        g_s[(size_t)b * L_ + t] = red[0][tl] + red[1][tl] + red[2][tl] + red[3][tl];
}

// ---- softmax mix + downsample ----
#define OT 32
__global__ __launch_bounds__(256) void epilogue_kernel(float* __restrict__ out) {
    __shared__ float att[2 * OT][3];
    const int b = blockIdx.y, o0 = blockIdx.x * OT, tid = threadIdx.x;
    const float* sp = g_s + (size_t)b * L_;

    if (tid < 2 * OT) {
        int l = 2 * o0 + tid;
        float c1 = sp[l];
        int n2 = l >> 1;
        float c2 = 0.5f * (sp[2 * n2] + sp[2 * n2 + 1]);
        int n3 = l / 3;
        float c3 = (n3 < NB3_) ? (sp[3 * n3] + sp[3 * n3 + 1] + sp[3 * n3 + 2]) * (1.f / 3.f) : 0.f;
        float m = fmaxf(c1, fmaxf(c2, c3));
        float a1 = __expf(c1 - m), a2 = __expf(c2 - m), a3 = __expf(c3 - m);
        float inv = 1.f / (a1 + a2 + a3);
        att[tid][0] = a1 * inv; att[tid][1] = a2 * inv; att[tid][2] = a3 * inv;
    }
    __syncthreads();

    const float* yb = g_y + (size_t)b * E_ * L_;
    const int ol = tid & (OT - 1), o = o0 + ol;
    const int l0 = 2 * o, l1 = l0 + 1;
    const int n3a = l0 / 3, n3b = l1 / 3;
    const bool ok3a = (n3a < NB3_), ok3b = (n3b < NB3_);
    const float w10 = att[2 * ol][0], w20 = att[2 * ol][1], w30 = att[2 * ol][2];
    const float w11 = att[2 * ol + 1][0], w21 = att[2 * ol + 1][1], w31 = att[2 * ol + 1][2];

    for (int e = tid / OT; e < E_; e += 256 / OT) {
        const float* yr = yb + (size_t)e * L_;
        float ya = yr[l0], yv = yr[l1];
        float v2 = 0.5f * (ya + yv);
        float v3a = ok3a ? (yr[3 * n3a] + yr[3 * n3a + 1] + yr[3 * n3a + 2]) * (1.f / 3.f) : 0.f;
        float v3b = (n3b == n3a) ? v3a
                  : (ok3b ? (yr[3 * n3b] + yr[3 * n3b + 1] + yr[3 * n3b + 2]) * (1.f / 3.f) : 0.f);
        out[((size_t)b * E_ + e) * (L_ / 2) + o] =
            0.5f * ((ya * w10 + v2 * w20 + v3a * w30) + (yv * w11 + v2 * w21 + v3b * w31));
    }
}

extern "C" void kernel_launch(void* const* d_in, const int* in_sizes, int n_in,
                              void* d_out, int out_size) {
    const float* x = (const float*)d_in[0];
    const float* conv_w = (const float*)d_in[1];
    const float* conv_b = (const float*)d_in[2];
    const float* score_w = (const float*)d_in[3];
    float* out = (float*)d_out;

    dim3 gt(L_ / 32, E_ / 32, B_);
    tsplit_x<<<gt, 256>>>(x);
    split_w<<<(E_ * KT_) / 256, 256>>>(conv_w);

    static int smem_set = 0;
    if (!smem_set) {
        cudaFuncSetAttribute(conv_mma, cudaFuncAttributeMaxDynamicSharedMemorySize, CSMEM);
        smem_set = 1;
    }
    dim3 gc(L_ / 256, E_ / 128, B_);   // 32 x 4 x 8 = 1024 CTAs
    conv_mma<<<gc, 512, CSMEM>>>(conv_b);

    dim3 gs(L_ / 64, B_);
    score_kernel<<<gs, 256>>>(score_w);

    dim3 ge((L_ / 2) / OT, B_);
    epilogue_kernel<<<ge, 256>>>(out);
}

// round 17
// speedup vs baseline: 2.3179x; 1.0334x over previous
#include <cuda_runtime.h>
#include <cstdint>
#include <cuda_fp16.h>

#define B_ 8
#define E_ 512
#define L_ 8192
#define KS_ 5
#define LC_ (L_ - KS_ + 1)   // 8188
#define NB3_ 2730
#define KT_ (E_ * KS_)       // 2560

// conv tiling: CTA 128eo x 256t, 16 warps of 64x32; K chunks of 32 (5 taps x 16 e-chunks)
// single-product fp16: A = W, B = X
#define NCH 80
#define ROWB 80                       // padded smem row stride (64B payload)
#define A_TILE (128 * ROWB)           // 10240, 3 stages
#define B_ROWS 260
#define B_TILE (B_ROWS * ROWB)        // 20800, double-buffered
#define OFF_B (3 * A_TILE)            // 30720
#define CSMEM (OFF_B + 2 * B_TILE)    // 72320

__device__ __align__(16) __half g_y[(size_t)B_ * E_ * L_];   // fp16 conv output
__device__ float g_s[(size_t)B_ * L_];
__device__ __align__(16) __half g_xt[(size_t)B_ * L_ * E_]; // [b][t][e]
__device__ __align__(16) __half g_w[(size_t)E_ * KT_];      // [eo][tap][ein]

__device__ __forceinline__ uint32_t smem_u32(const void* p) {
    uint32_t a;
    asm("{ .reg .u64 t; cvta.to.shared.u64 t, %1; cvt.u32.u64 %0, t; }" : "=r"(a) : "l"(p));
    return a;
}
#define CP16(dst, src) \
    asm volatile("cp.async.cg.shared.global [%0], [%1], 16;" :: "r"(dst), "l"(src) : "memory")
#define CP_COMMIT() asm volatile("cp.async.commit_group;" ::: "memory")
#define CP_WAIT1() asm volatile("cp.async.wait_group 1;" ::: "memory")

#define LDSM4(r, a) \
    asm volatile("ldmatrix.sync.aligned.m8n8.x4.shared.b16 {%0,%1,%2,%3}, [%4];" \
        : "=r"((r)[0]), "=r"((r)[1]), "=r"((r)[2]), "=r"((r)[3]) : "r"(a))

#define MMA(c, A, b0, b1) \
    asm volatile("mma.sync.aligned.m16n8k16.row.col.f32.f16.f16.f32 " \
        "{%0,%1,%2,%3},{%4,%5,%6,%7},{%8,%9},{%0,%1,%2,%3};" \
        : "+f"((c)[0]), "+f"((c)[1]), "+f"((c)[2]), "+f"((c)[3]) \
        : "r"((A)[0]), "r"((A)[1]), "r"((A)[2]), "r"((A)[3]), "r"(b0), "r"(b1))

// ---- transpose + fp16 quantize of x: [b][e][t] f32 -> [b][t][e] ----
__global__ __launch_bounds__(256) void tsplit_x(const float* __restrict__ x) {
    __shared__ float tile[32][33];
    const int b = blockIdx.z, t0 = blockIdx.x * 32, e0 = blockIdx.y * 32;
    const int tx = threadIdx.x & 31, ty = threadIdx.x >> 5;
#pragma unroll
    for (int p = 0; p < 4; p++)
        tile[ty + 8 * p][tx] = x[((size_t)b * E_ + e0 + ty + 8 * p) * L_ + t0 + tx];
    __syncthreads();
#pragma unroll
    for (int p = 0; p < 4; p++) {
        int t = t0 + ty + 8 * p;
        g_xt[((size_t)b * L_ + t) * E_ + e0 + tx] = __float2half(tile[tx][ty + 8 * p]);
    }
}

// ---- weight re-layout: w[eo][ein][tap] -> [eo][tap][ein] fp16 ----
__global__ __launch_bounds__(256) void split_w(const float* __restrict__ w) {
    int i = blockIdx.x * 256 + threadIdx.x;
    int eo = i / KT_;
    int r = i - eo * KT_;
    int tap = r >> 9, ei = r & 511;
    g_w[i] = __float2half(w[(size_t)eo * KT_ + ei * KS_ + tap]);
}

// ---- conv: C[eo 128][t 256], 16 warps (64x32), single-product fp16 ----
__global__ __launch_bounds__(512, 1) void conv_mma(const float* __restrict__ bias) {
    extern __shared__ __align__(16) char sm[];
    const uint32_t sb = smem_u32(sm);
    const int tid = threadIdx.x, lane = tid & 31, wid = tid >> 5;
    const int wm = wid & 1;        // eo 64-half
    const int wn = wid >> 1;       // t 32-block (0..7)
    const int b = blockIdx.z, t0 = blockIdx.x * 256, eo0 = blockIdx.y * 128;

    float acc[4][4][4];
#pragma unroll
    for (int i = 0; i < 4; i++)
#pragma unroll
        for (int j = 0; j < 4; j++)
#pragma unroll
            for (int q = 0; q < 4; q++) acc[i][j][q] = 0.f;

    const int lrow = tid >> 2, lq = tid & 3;   // 128 loader rows x 4 16B-chunks

    auto issue = [&](int c) {
        const int tap = c % KS_, ec = c / KS_;
        const uint32_t stA = sb + (c % 3) * A_TILE;
        const size_t woff = (size_t)(eo0 + lrow) * KT_ + tap * 512 + ec * 32 + lq * 8;
        CP16(stA + lrow * ROWB + lq * 16, g_w + woff);
        if (tap == 0) {
            const uint32_t stB = sb + OFF_B + (ec & 1) * B_TILE;
#pragma unroll
            for (int h = 0; h < 2; h++) {
                int r = lrow + h * 128;
                int t = t0 + r; if (t > L_ - 1) t = L_ - 1;
                CP16(stB + r * ROWB + lq * 16,
                     g_xt + ((size_t)b * L_ + t) * E_ + ec * 32 + lq * 8);
            }
            if (lrow < 4) {
                int r = 256 + lrow;
                int t = t0 + r; if (t > L_ - 1) t = L_ - 1;
                CP16(stB + r * ROWB + lq * 16,
                     g_xt + ((size_t)b * L_ + t) * E_ + ec * 32 + lq * 8);
            }
        }
    };

    issue(0); CP_COMMIT();
    issue(1); CP_COMMIT();

    const int lr = lane & 7, g = lane >> 3;

    for (int c = 0; c < NCH; c++) {
        CP_WAIT1();        // group c landed (only c+1 may remain in flight)
        __syncthreads();   // protects stage (c+2)%3 overwrites issued below

        const int tap = c % KS_;
        const uint32_t stA = sb + (c % 3) * A_TILE;
        const uint32_t stB = sb + OFF_B + ((c / KS_) & 1) * B_TILE;

        uint32_t bf[2][4][2];   // B frags double-buffered across kk
        auto loadB = [&](int kk) {
#pragma unroll
            for (int j = 0; j < 2; j++) {
                uint32_t rb = stB
                    + (uint32_t)(tap + wn * 32 + j * 16 + lr + (g >> 1) * 8) * ROWB
                    + kk * 32 + (g & 1) * 16;
                uint32_t r4[4];
                LDSM4(r4, rb);
                bf[kk][2 * j][0] = r4[0]; bf[kk][2 * j][1] = r4[1];
                bf[kk][2 * j + 1][0] = r4[2]; bf[kk][2 * j + 1][1] = r4[3];
            }
        };

        loadB(0);
#pragma unroll
        for (int kk = 0; kk < 2; kk++) {
            uint32_t af[4][4];
#pragma unroll
            for (int i = 0; i < 4; i++) {
                uint32_t ra = stA + (uint32_t)(wm * 64 + i * 16 + lr + (g & 1) * 8) * ROWB
                              + kk * 32 + (g >> 1) * 16;
                LDSM4(af[i], ra);
            }
            if (kk == 0) loadB(1);   // prefetch next-kk B under the MMAs
#pragma unroll
            for (int i = 0; i < 4; i++)
#pragma unroll
                for (int j = 0; j < 4; j++)
                    MMA(acc[i][j], af[i], bf[kk][j][0], bf[kk][j][1]);
        }

        if (c + 2 < NCH) issue(c + 2);
        CP_COMMIT();
    }

    // store: acc -> g_y (fp16) + bias, zero for t >= LC_
    const int l4 = lane >> 2, l2 = (lane & 3) * 2;
#pragma unroll
    for (int i = 0; i < 4; i++) {
        int eoA = eo0 + wm * 64 + i * 16 + l4;
        float bv0 = bias[eoA], bv1 = bias[eoA + 8];
        __half* p0 = g_y + ((size_t)b * E_ + eoA) * L_;
        __half* p1 = p0 + (size_t)8 * L_;
#pragma unroll
        for (int j = 0; j < 4; j++) {
            int tc = t0 + wn * 32 + j * 8 + l2;
            float y00 = (tc     < LC_) ? acc[i][j][0] + bv0 : 0.f;
            float y01 = (tc + 1 < LC_) ? acc[i][j][1] + bv0 : 0.f;
            float y10 = (tc     < LC_) ? acc[i][j][2] + bv1 : 0.f;
            float y11 = (tc + 1 < LC_) ? acc[i][j][3] + bv1 : 0.f;
            *reinterpret_cast<__half2*>(p0 + tc) = __floats2half2_rn(y00, y01);
            *reinterpret_cast<__half2*>(p1 + tc) = __floats2half2_rn(y10, y11);
        }
    }
}

// ---- scores s[b,t] = <y[b,:,t], score_w>, 4-way e-split ----
__global__ __launch_bounds__(256) void score_kernel(const float* __restrict__ sw) {
    __shared__ float swv[E_];
    __shared__ float red[4][64];
    const int tid = threadIdx.x;
    const int b = blockIdx.y;
    const int tl = tid & 63;
    const int eg = tid >> 6;
    const int t = blockIdx.x * 64 + tl;
    for (int i = tid; i < E_; i += 256) swv[i] = sw[i];
    __syncthreads();
    const __half* yb = g_y + (size_t)b * E_ * L_ + (size_t)eg * 128 * L_ + t;
    float acc = 0.f;
#pragma unroll 16
    for (int e = 0; e < 128; e++) acc += __half2float(yb[(size_t)e * L_]) * swv[eg * 128 + e];
    red[eg][tl] = acc;
    __syncthreads();
    if (eg == 0)
        g_s[(size_t)b * L_ + t] = red[0][tl] + red[1][tl] + red[2][tl] + red[3][tl];
}

// ---- softmax mix + downsample ----
#define OT 32
__global__ __launch_bounds__(256) void epilogue_kernel(float* __restrict__ out) {
    __shared__ float att[2 * OT][3];
    const int b = blockIdx.y, o0 = blockIdx.x * OT, tid = threadIdx.x;
    const float* sp = g_s + (size_t)b * L_;

    if (tid < 2 * OT) {
        int l = 2 * o0 + tid;
        float c1 = sp[l];
        int n2 = l >> 1;
        float c2 = 0.5f * (sp[2 * n2] + sp[2 * n2 + 1]);
        int n3 = l / 3;
        float c3 = (n3 < NB3_) ? (sp[3 * n3] + sp[3 * n3 + 1] + sp[3 * n3 + 2]) * (1.f / 3.f) : 0.f;
        float m = fmaxf(c1, fmaxf(c2, c3));
        float a1 = __expf(c1 - m), a2 = __expf(c2 - m), a3 = __expf(c3 - m);
        float inv = 1.f / (a1 + a2 + a3);
        att[tid][0] = a1 * inv; att[tid][1] = a2 * inv; att[tid][2] = a3 * inv;
    }
    __syncthreads();

    const __half* yb = g_y + (size_t)b * E_ * L_;
    const int ol = tid & (OT - 1), o = o0 + ol;
    const int l0 = 2 * o, l1 = l0 + 1;
    const int n3a = l0 / 3, n3b = l1 / 3;
    const bool ok3a = (n3a < NB3_), ok3b = (n3b < NB3_);
    const float w10 = att[2 * ol][0], w20 = att[2 * ol][1], w30 = att[2 * ol][2];
    const float w11 = att[2 * ol + 1][0], w21 = att[2 * ol + 1][1], w31 = att[2 * ol + 1][2];

    for (int e = tid / OT; e < E_; e += 256 / OT) {
        const __half* yr = yb + (size_t)e * L_;
        __half2 p = *reinterpret_cast<const __half2*>(yr + l0);   // l0 even
        float ya = __low2float(p), yv = __high2float(p);
        float v2 = 0.5f * (ya + yv);
        float v3a = ok3a ? (__half2float(yr[3 * n3a]) + __half2float(yr[3 * n3a + 1])
                            + __half2float(yr[3 * n3a + 2])) * (1.f / 3.f) : 0.f;
        float v3b = (n3b == n3a) ? v3a
                  : (ok3b ? (__half2float(yr[3 * n3b]) + __half2float(yr[3 * n3b + 1])
                             + __half2float(yr[3 * n3b + 2])) * (1.f / 3.f) : 0.f);
        out[((size_t)b * E_ + e) * (L_ / 2) + o] =
            0.5f * ((ya * w10 + v2 * w20 + v3a * w30) + (yv * w11 + v2 * w21 + v3b * w31));
    }
}

extern "C" void kernel_launch(void* const* d_in, const int* in_sizes, int n_in,
                              void* d_out, int out_size) {
    const float* x = (const float*)d_in[0];
    const float* conv_w = (const float*)d_in[1];
    const float* conv_b = (const float*)d_in[2];
    const float* score_w = (const float*)d_in[3];
    float* out = (float*)d_out;

    dim3 gt(L_ / 32, E_ / 32, B_);
    tsplit_x<<<gt, 256>>>(x);
    split_w<<<(E_ * KT_) / 256, 256>>>(conv_w);

    static int smem_set = 0;
    if (!smem_set) {
        cudaFuncSetAttribute(conv_mma, cudaFuncAttributeMaxDynamicSharedMemorySize, CSMEM);
        smem_set = 1;
    }
    dim3 gc(L_ / 256, E_ / 128, B_);   // 32 x 4 x 8 = 1024 CTAs
    conv_mma<<<gc, 512, CSMEM>>>(conv_b);

    dim3 gs(L_ / 64, B_);
    score_kernel<<<gs, 256>>>(score_w);

    dim3 ge((L_ / 2) / OT, B_);
    epilogue_kernel<<<ge, 256>>>(out);
}